// round 3
// baseline (speedup 1.0000x reference)
#include <cuda_runtime.h>
#include <cuda_bf16.h>

#define N_NODES 50000
#define N_EDGES 800000
#define F1 128
#define F2 16

// Scratch (allocation-free contract: __device__ globals).
// Vector-accessed arrays are declared as float4 so 128-bit LDG/STG are
// guaranteed aligned.
__device__ int    g_cnt [N_NODES];
__device__ int    g_off [N_NODES + 1];
__device__ int    g_fill[N_NODES];
__device__ int    g_src [N_EDGES];
__device__ float  g_dinv[N_NODES];
__device__ float4 g_h1  [N_NODES * (F1 / 4)];   // [N,128] as float4[N*32]
__device__ float4 g_h2  [N_NODES * (F2 / 4)];   // [N,16]  as float4[N*4]

// ---------------------------------------------------------------------------
// 0) zero the CSR build state (graph replays -> must reset every call)
// ---------------------------------------------------------------------------
__global__ void k_init() {
    int i = blockIdx.x * blockDim.x + threadIdx.x;
    if (i < N_NODES) { g_cnt[i] = 0; g_fill[i] = 0; }
}

// ---------------------------------------------------------------------------
// 1) in-degree counts over destination (col) nodes  [edge_index is int32]
// ---------------------------------------------------------------------------
__global__ void k_count(const int* __restrict__ ei) {
    int e = blockIdx.x * blockDim.x + threadIdx.x;
    if (e < N_EDGES) {
        unsigned c = (unsigned)ei[N_EDGES + e];
        if (c < N_NODES) atomicAdd(&g_cnt[c], 1);
    }
}

// ---------------------------------------------------------------------------
// 2) dinv = rsqrt(cnt + 1)   (+1 = self loop; deg >= 1 always)
// ---------------------------------------------------------------------------
__global__ void k_dinv() {
    int i = blockIdx.x * blockDim.x + threadIdx.x;
    if (i < N_NODES) g_dinv[i] = rsqrtf((float)(g_cnt[i] + 1));
}

// ---------------------------------------------------------------------------
// 3) exclusive scan of counts -> offsets (single block, 1024 threads)
// ---------------------------------------------------------------------------
#define SCAN_T 1024
#define CHUNK  49     // 1024*49 = 50176 >= 50000
__global__ __launch_bounds__(SCAN_T) void k_scan() {
    __shared__ int sh[SCAN_T];
    int t  = threadIdx.x;
    int lo = t * CHUNK;
    int hi = min(lo + CHUNK, N_NODES);

    int s = 0;
    for (int i = lo; i < hi; i++) s += g_cnt[i];
    sh[t] = s;
    __syncthreads();

    for (int off = 1; off < SCAN_T; off <<= 1) {
        int v = (t >= off) ? sh[t - off] : 0;
        __syncthreads();
        sh[t] += v;
        __syncthreads();
    }

    int run = (t > 0) ? sh[t - 1] : 0;
    for (int i = lo; i < hi; i++) { g_off[i] = run; run += g_cnt[i]; }
    if (t == SCAN_T - 1) g_off[N_NODES] = run;
}

// ---------------------------------------------------------------------------
// 4) fill per-destination source lists
// ---------------------------------------------------------------------------
__global__ void k_fill(const int* __restrict__ ei) {
    int e = blockIdx.x * blockDim.x + threadIdx.x;
    if (e < N_EDGES) {
        unsigned r = (unsigned)ei[e];
        unsigned c = (unsigned)ei[N_EDGES + e];
        if (r < N_NODES && c < N_NODES) {
            int pos = g_off[c] + atomicAdd(&g_fill[c], 1);
            g_src[pos] = (int)r;
        }
    }
}

// ---------------------------------------------------------------------------
// 5) h1 = x @ W1    [50000,128] x [128,128]
//    64 rows/block, 256 threads, 8x4 micro-tile per thread.
// ---------------------------------------------------------------------------
__global__ __launch_bounds__(256) void k_gemm1(const float* __restrict__ x,
                                               const float* __restrict__ W) {
    __shared__ float xs[64][F1];
    const int row0 = blockIdx.x * 64;
    const int tid  = threadIdx.x;

    for (int i = tid; i < 64 * 32; i += 256) {
        int r  = i >> 5;
        int c4 = i & 31;
        float4 v = make_float4(0.f, 0.f, 0.f, 0.f);
        if (row0 + r < N_NODES)
            v = ((const float4*)x)[(size_t)(row0 + r) * 32 + c4];  // x is harness buf, aligned
        xs[r][c4 * 4 + 0] = v.x;
        xs[r][c4 * 4 + 1] = v.y;
        xs[r][c4 * 4 + 2] = v.z;
        xs[r][c4 * 4 + 3] = v.w;
    }
    __syncthreads();

    const int tx = tid & 31;    // cols 4*tx .. 4*tx+3
    const int ty = tid >> 5;    // rows 8*ty .. 8*ty+7

    float acc[8][4];
    #pragma unroll
    for (int r = 0; r < 8; r++)
        #pragma unroll
        for (int q = 0; q < 4; q++) acc[r][q] = 0.f;

    #pragma unroll 4
    for (int k = 0; k < F1; k++) {
        float4 w = ((const float4*)W)[k * 32 + tx];
        #pragma unroll
        for (int r = 0; r < 8; r++) {
            float xv = xs[ty * 8 + r][k];
            acc[r][0] = fmaf(xv, w.x, acc[r][0]);
            acc[r][1] = fmaf(xv, w.y, acc[r][1]);
            acc[r][2] = fmaf(xv, w.z, acc[r][2]);
            acc[r][3] = fmaf(xv, w.w, acc[r][3]);
        }
    }

    #pragma unroll
    for (int r = 0; r < 8; r++) {
        int gr = row0 + ty * 8 + r;
        if (gr < N_NODES)
            g_h1[gr * 32 + tx] =
                make_float4(acc[r][0], acc[r][1], acc[r][2], acc[r][3]);
    }
}

// ---------------------------------------------------------------------------
// 6) fused layer-1: gather-aggregate + self-loop + bias + ReLU + @W2
//    one warp per destination node; lane covers 4 of 128 feature cols.
// ---------------------------------------------------------------------------
__global__ __launch_bounds__(256) void k_layer1(const float* __restrict__ b1,
                                                const float* __restrict__ W2) {
    int row  = (blockIdx.x * 256 + threadIdx.x) >> 5;
    int lane = threadIdx.x & 31;
    if (row >= N_NODES) return;

    float dc = g_dinv[row];
    float d2 = dc * dc;

    float4 h   = g_h1[row * 32 + lane];
    float4 acc = make_float4(h.x * d2, h.y * d2, h.z * d2, h.w * d2);

    int e0 = g_off[row], e1 = g_off[row + 1];
    for (int e = e0; e < e1; e++) {
        int   r = g_src[e];                 // warp-uniform -> broadcast
        float w = g_dinv[r] * dc;
        float4 v = g_h1[r * 32 + lane];
        acc.x = fmaf(v.x, w, acc.x);
        acc.y = fmaf(v.y, w, acc.y);
        acc.z = fmaf(v.z, w, acc.z);
        acc.w = fmaf(v.w, w, acc.w);
    }

    float4 b = ((const float4*)b1)[lane];
    float v[4];
    v[0] = fmaxf(acc.x + b.x, 0.f);
    v[1] = fmaxf(acc.y + b.y, 0.f);
    v[2] = fmaxf(acc.z + b.z, 0.f);
    v[3] = fmaxf(acc.w + b.w, 0.f);

    // h2[row] = relu_row @ W2   (warp butterfly over 128-dim)
    float p[16];
    #pragma unroll
    for (int j = 0; j < 16; j++) p[j] = 0.f;

    #pragma unroll
    for (int q = 0; q < 4; q++) {
        int k = lane * 4 + q;
        #pragma unroll
        for (int j4 = 0; j4 < 4; j4++) {
            float4 ww = ((const float4*)W2)[k * 4 + j4];
            p[j4 * 4 + 0] = fmaf(v[q], ww.x, p[j4 * 4 + 0]);
            p[j4 * 4 + 1] = fmaf(v[q], ww.y, p[j4 * 4 + 1]);
            p[j4 * 4 + 2] = fmaf(v[q], ww.z, p[j4 * 4 + 2]);
            p[j4 * 4 + 3] = fmaf(v[q], ww.w, p[j4 * 4 + 3]);
        }
    }

    #pragma unroll
    for (int off = 16; off >= 1; off >>= 1)
        #pragma unroll
        for (int j = 0; j < 16; j++)
            p[j] += __shfl_xor_sync(0xffffffffu, p[j], off);

    if (lane < 16) ((float*)g_h2)[row * F2 + lane] = p[lane];
}

// ---------------------------------------------------------------------------
// 7) fused layer-2: gather-aggregate + self-loop + bias + log_softmax
//    one warp per node; j = lane & 15 (both half-warps mirror)
// ---------------------------------------------------------------------------
__global__ __launch_bounds__(256) void k_layer2(const float* __restrict__ b2,
                                                float* __restrict__ out) {
    int row  = (blockIdx.x * 256 + threadIdx.x) >> 5;
    int lane = threadIdx.x & 31;
    if (row >= N_NODES) return;

    int j = lane & 15;
    float dc = g_dinv[row];
    float d2 = dc * dc;

    const float* h2 = (const float*)g_h2;
    float acc = h2[row * F2 + j] * d2;

    int e0 = g_off[row], e1 = g_off[row + 1];
    for (int e = e0; e < e1; e++) {
        int   r = g_src[e];
        float w = g_dinv[r] * dc;
        acc = fmaf(h2[r * F2 + j], w, acc);
    }
    acc += b2[j];

    float m = acc;
    #pragma unroll
    for (int off = 8; off >= 1; off >>= 1)
        m = fmaxf(m, __shfl_xor_sync(0xffffffffu, m, off));

    float s = __expf(acc - m);
    #pragma unroll
    for (int off = 8; off >= 1; off >>= 1)
        s += __shfl_xor_sync(0xffffffffu, s, off);

    if (lane < 16) out[row * F2 + lane] = (acc - m) - logf(s);
}

// ---------------------------------------------------------------------------
extern "C" void kernel_launch(void* const* d_in, const int* in_sizes, int n_in,
                              void* d_out, int out_size) {
    const float* x  = (const float*)d_in[0];
    const int*   ei = (const int*)d_in[1];     // int32! (JAX x64 disabled)
    const float* W1 = (const float*)d_in[2];
    const float* b1 = (const float*)d_in[3];
    const float* W2 = (const float*)d_in[4];
    const float* b2 = (const float*)d_in[5];
    float* out = (float*)d_out;

    (void)in_sizes; (void)n_in; (void)out_size;

    k_init  <<<(N_NODES + 255) / 256, 256>>>();
    k_count <<<(N_EDGES + 255) / 256, 256>>>(ei);
    k_dinv  <<<(N_NODES + 255) / 256, 256>>>();
    k_scan  <<<1, SCAN_T>>>();
    k_fill  <<<(N_EDGES + 255) / 256, 256>>>(ei);
    k_gemm1 <<<(N_NODES + 63) / 64, 256>>>(x, W1);
    k_layer1<<<(N_NODES * 32 + 255) / 256, 256>>>(b1, W2);
    k_layer2<<<(N_NODES * 32 + 255) / 256, 256>>>(b2, out);
}

// round 5
// speedup vs baseline: 1.1922x; 1.1922x over previous
#include <cuda_runtime.h>
#include <cuda_bf16.h>

#define N_NODES 50000
#define N_EDGES 800000
#define F1 128
#define F2 16

#define TILE 512
#define NB   ((N_NODES + TILE - 1) / TILE)   // 98

// Scratch (allocation-free contract: __device__ globals)
__device__ int    g_cnt [N_NODES];
__device__ int    g_off [N_NODES];      // exclusive offsets; mutated by fill
__device__ int    g_bsum[NB];
__device__ int    g_bpre[NB];
__device__ int    g_src [N_EDGES];
__device__ float  g_dinv[N_NODES];
__device__ float4 g_h1  [N_NODES * (F1 / 4)];
__device__ float4 g_h2  [N_NODES * (F2 / 4)];

// ---------------------------------------------------------------------------
// 0) zero CSR counters (graph replays -> must reset every call)
// ---------------------------------------------------------------------------
__global__ void k_init() {
    int i = blockIdx.x * blockDim.x + threadIdx.x;
    if (i < N_NODES) g_cnt[i] = 0;
}

// ---------------------------------------------------------------------------
// 1) in-degree counts over destination (col) nodes  [edge_index is int32]
// ---------------------------------------------------------------------------
__global__ void k_count(const int* __restrict__ ei) {
    int e = blockIdx.x * blockDim.x + threadIdx.x;
    if (e < N_EDGES) {
        unsigned c = (unsigned)ei[N_EDGES + e];
        if (c < N_NODES) atomicAdd(&g_cnt[c], 1);
    }
}

// ---------------------------------------------------------------------------
// 2a) per-tile sums (+ fused dinv = rsqrt(deg+1))
// ---------------------------------------------------------------------------
__global__ __launch_bounds__(TILE) void k_scanA() {
    __shared__ int sh[TILE];
    int t = threadIdx.x;
    int i = blockIdx.x * TILE + t;
    int c = (i < N_NODES) ? g_cnt[i] : 0;
    if (i < N_NODES) g_dinv[i] = rsqrtf((float)(c + 1));
    sh[t] = c;
    __syncthreads();
    #pragma unroll
    for (int off = TILE / 2; off >= 1; off >>= 1) {
        if (t < off) sh[t] += sh[t + off];
        __syncthreads();
    }
    if (t == 0) g_bsum[blockIdx.x] = sh[0];
}

// ---------------------------------------------------------------------------
// 2b) exclusive scan over NB partials (1 block, 128 threads)
// ---------------------------------------------------------------------------
__global__ __launch_bounds__(128) void k_scanB() {
    __shared__ int sh[128];
    int t = threadIdx.x;
    int v = (t < NB) ? g_bsum[t] : 0;
    sh[t] = v;
    __syncthreads();
    #pragma unroll
    for (int off = 1; off < 128; off <<= 1) {
        int u = (t >= off) ? sh[t - off] : 0;
        __syncthreads();
        sh[t] += u;
        __syncthreads();
    }
    if (t < NB) g_bpre[t] = (t > 0) ? sh[t - 1] : 0;
}

// ---------------------------------------------------------------------------
// 2c) in-tile exclusive scan + tile prefix -> g_off
// ---------------------------------------------------------------------------
__global__ __launch_bounds__(TILE) void k_scanC() {
    __shared__ int sh[TILE];
    int t = threadIdx.x;
    int i = blockIdx.x * TILE + t;
    int c = (i < N_NODES) ? g_cnt[i] : 0;
    sh[t] = c;
    __syncthreads();
    #pragma unroll
    for (int off = 1; off < TILE; off <<= 1) {
        int u = (t >= off) ? sh[t - off] : 0;
        __syncthreads();
        sh[t] += u;
        __syncthreads();
    }
    if (i < N_NODES)
        g_off[i] = g_bpre[blockIdx.x] + ((t > 0) ? sh[t - 1] : 0);
}

// ---------------------------------------------------------------------------
// 3) fill source lists; atomically bumps g_off[c] (slot = returned value).
//    After this kernel g_off[c] == original off[c+1].
// ---------------------------------------------------------------------------
__global__ void k_fill(const int* __restrict__ ei) {
    int e = blockIdx.x * blockDim.x + threadIdx.x;
    if (e < N_EDGES) {
        unsigned r = (unsigned)ei[e];
        unsigned c = (unsigned)ei[N_EDGES + e];
        if (r < N_NODES && c < N_NODES) {
            int pos = atomicAdd(&g_off[c], 1);
            g_src[pos] = (int)r;
        }
    }
}

// ---------------------------------------------------------------------------
// 4) h1 = x @ W1    [50000,128] x [128,128]
// ---------------------------------------------------------------------------
__global__ __launch_bounds__(256) void k_gemm1(const float* __restrict__ x,
                                               const float* __restrict__ W) {
    __shared__ float xs[64][F1];
    const int row0 = blockIdx.x * 64;
    const int tid  = threadIdx.x;

    for (int i = tid; i < 64 * 32; i += 256) {
        int r  = i >> 5;
        int c4 = i & 31;
        float4 v = make_float4(0.f, 0.f, 0.f, 0.f);
        if (row0 + r < N_NODES)
            v = ((const float4*)x)[(size_t)(row0 + r) * 32 + c4];
        xs[r][c4 * 4 + 0] = v.x;
        xs[r][c4 * 4 + 1] = v.y;
        xs[r][c4 * 4 + 2] = v.z;
        xs[r][c4 * 4 + 3] = v.w;
    }
    __syncthreads();

    const int tx = tid & 31;
    const int ty = tid >> 5;

    float acc[8][4];
    #pragma unroll
    for (int r = 0; r < 8; r++)
        #pragma unroll
        for (int q = 0; q < 4; q++) acc[r][q] = 0.f;

    #pragma unroll 4
    for (int k = 0; k < F1; k++) {
        float4 w = ((const float4*)W)[k * 32 + tx];
        #pragma unroll
        for (int r = 0; r < 8; r++) {
            float xv = xs[ty * 8 + r][k];
            acc[r][0] = fmaf(xv, w.x, acc[r][0]);
            acc[r][1] = fmaf(xv, w.y, acc[r][1]);
            acc[r][2] = fmaf(xv, w.z, acc[r][2]);
            acc[r][3] = fmaf(xv, w.w, acc[r][3]);
        }
    }

    #pragma unroll
    for (int r = 0; r < 8; r++) {
        int gr = row0 + ty * 8 + r;
        if (gr < N_NODES)
            g_h1[gr * 32 + tx] =
                make_float4(acc[r][0], acc[r][1], acc[r][2], acc[r][3]);
    }
}

// ---------------------------------------------------------------------------
// 5) fused layer-1: gather-aggregate + self-loop + bias + ReLU + @W2
// ---------------------------------------------------------------------------
__global__ __launch_bounds__(256) void k_layer1(const float* __restrict__ b1,
                                                const float* __restrict__ W2) {
    int row  = (blockIdx.x * 256 + threadIdx.x) >> 5;
    int lane = threadIdx.x & 31;
    if (row >= N_NODES) return;

    float dc = g_dinv[row];
    float d2 = dc * dc;

    float4 h   = g_h1[row * 32 + lane];
    float4 acc = make_float4(h.x * d2, h.y * d2, h.z * d2, h.w * d2);

    int e0 = (row > 0) ? g_off[row - 1] : 0;
    int e1 = g_off[row];
    for (int e = e0; e < e1; e++) {
        int   r = g_src[e];
        float w = g_dinv[r] * dc;
        float4 v = g_h1[r * 32 + lane];
        acc.x = fmaf(v.x, w, acc.x);
        acc.y = fmaf(v.y, w, acc.y);
        acc.z = fmaf(v.z, w, acc.z);
        acc.w = fmaf(v.w, w, acc.w);
    }

    float4 b = ((const float4*)b1)[lane];
    float v[4];
    v[0] = fmaxf(acc.x + b.x, 0.f);
    v[1] = fmaxf(acc.y + b.y, 0.f);
    v[2] = fmaxf(acc.z + b.z, 0.f);
    v[3] = fmaxf(acc.w + b.w, 0.f);

    float p[16];
    #pragma unroll
    for (int j = 0; j < 16; j++) p[j] = 0.f;

    #pragma unroll
    for (int q = 0; q < 4; q++) {
        int k = lane * 4 + q;
        #pragma unroll
        for (int j4 = 0; j4 < 4; j4++) {
            float4 ww = ((const float4*)W2)[k * 4 + j4];
            p[j4 * 4 + 0] = fmaf(v[q], ww.x, p[j4 * 4 + 0]);
            p[j4 * 4 + 1] = fmaf(v[q], ww.y, p[j4 * 4 + 1]);
            p[j4 * 4 + 2] = fmaf(v[q], ww.z, p[j4 * 4 + 2]);
            p[j4 * 4 + 3] = fmaf(v[q], ww.w, p[j4 * 4 + 3]);
        }
    }

    #pragma unroll
    for (int off = 16; off >= 1; off >>= 1)
        #pragma unroll
        for (int j = 0; j < 16; j++)
            p[j] += __shfl_xor_sync(0xffffffffu, p[j], off);

    if (lane < 16) ((float*)g_h2)[row * F2 + lane] = p[lane];
}

// ---------------------------------------------------------------------------
// 6) fused layer-2: gather-aggregate + self-loop + bias + log_softmax
// ---------------------------------------------------------------------------
__global__ __launch_bounds__(256) void k_layer2(const float* __restrict__ b2,
                                                float* __restrict__ out) {
    int row  = (blockIdx.x * 256 + threadIdx.x) >> 5;
    int lane = threadIdx.x & 31;
    if (row >= N_NODES) return;

    int j = lane & 15;
    float dc = g_dinv[row];
    float d2 = dc * dc;

    const float* h2 = (const float*)g_h2;
    float acc = h2[row * F2 + j] * d2;

    int e0 = (row > 0) ? g_off[row - 1] : 0;
    int e1 = g_off[row];
    for (int e = e0; e < e1; e++) {
        int   r = g_src[e];
        float w = g_dinv[r] * dc;
        acc = fmaf(h2[r * F2 + j], w, acc);
    }
    acc += b2[j];

    float m = acc;
    #pragma unroll
    for (int off = 8; off >= 1; off >>= 1)
        m = fmaxf(m, __shfl_xor_sync(0xffffffffu, m, off));

    float s = __expf(acc - m);
    #pragma unroll
    for (int off = 8; off >= 1; off >>= 1)
        s += __shfl_xor_sync(0xffffffffu, s, off);

    if (lane < 16) out[row * F2 + lane] = (acc - m) - logf(s);
}

// ---------------------------------------------------------------------------
extern "C" void kernel_launch(void* const* d_in, const int* in_sizes, int n_in,
                              void* d_out, int out_size) {
    const float* x  = (const float*)d_in[0];
    const int*   ei = (const int*)d_in[1];     // int32 (JAX x64 disabled)
    const float* W1 = (const float*)d_in[2];
    const float* b1 = (const float*)d_in[3];
    const float* W2 = (const float*)d_in[4];
    const float* b2 = (const float*)d_in[5];
    float* out = (float*)d_out;

    (void)in_sizes; (void)n_in; (void)out_size;

    k_init  <<<(N_NODES + 255) / 256, 256>>>();
    k_count <<<(N_EDGES + 255) / 256, 256>>>(ei);
    k_scanA <<<NB, TILE>>>();
    k_scanB <<<1, 128>>>();
    k_scanC <<<NB, TILE>>>();
    k_fill  <<<(N_EDGES + 255) / 256, 256>>>(ei);
    k_gemm1 <<<(N_NODES + 63) / 64, 256>>>(x, W1);
    k_layer1<<<(N_NODES * 32 + 255) / 256, 256>>>(b1, W2);
    k_layer2<<<(N_NODES * 32 + 255) / 256, 256>>>(b2, out);
}

// round 6
// speedup vs baseline: 1.2919x; 1.0836x over previous
#include <cuda_runtime.h>
#include <cuda_bf16.h>

#define N_NODES 50000
#define N_EDGES 800000
#define F1 128
#define F2 16

#define TILE 512
#define NB   ((N_NODES + TILE - 1) / TILE)   // 98

// Scratch (allocation-free contract: __device__ globals)
__device__ int       g_cnt [N_NODES];        // zero at module load; self-re-zeroed
__device__ int       g_off [N_NODES];        // exclusive offsets; mutated by fill
__device__ long long g_state[NB];            // scan lookback: [63:32]=flag [31:0]=val
__device__ int       g_src [N_EDGES];
__device__ float     g_dinv[N_NODES];
__device__ float4    g_h1  [N_NODES * (F1 / 4)];
__device__ float4    g_h2  [N_NODES * (F2 / 4)];

// ---------------------------------------------------------------------------
// 1) in-degree counts (edge_index int32; col = second half). int4 reads.
// ---------------------------------------------------------------------------
__global__ void k_count(const int* __restrict__ ei) {
    int e4 = blockIdx.x * blockDim.x + threadIdx.x;
    if (e4 < N_EDGES / 4) {
        int4 c = ((const int4*)(ei + N_EDGES))[e4];
        if ((unsigned)c.x < N_NODES) atomicAdd(&g_cnt[c.x], 1);
        if ((unsigned)c.y < N_NODES) atomicAdd(&g_cnt[c.y], 1);
        if ((unsigned)c.z < N_NODES) atomicAdd(&g_cnt[c.z], 1);
        if ((unsigned)c.w < N_NODES) atomicAdd(&g_cnt[c.w], 1);
    }
}

// ---------------------------------------------------------------------------
// 2) single-kernel scan: block scans + decoupled lookback.
//    Fused: dinv = rsqrt(cnt+1); g_cnt self-zeroed (replay determinism).
//    98 blocks <= 148 SMs -> all resident wave-1 -> lookback is safe.
// ---------------------------------------------------------------------------
__global__ __launch_bounds__(TILE) void k_scan() {
    __shared__ int sh[TILE];
    __shared__ int s_ex;
    int t = threadIdx.x, bid = blockIdx.x;
    int i = bid * TILE + t;

    int c = (i < N_NODES) ? g_cnt[i] : 0;
    if (i < N_NODES) { g_dinv[i] = rsqrtf((float)(c + 1)); g_cnt[i] = 0; }

    sh[t] = c;
    __syncthreads();
    #pragma unroll
    for (int off = 1; off < TILE; off <<= 1) {
        int u = (t >= off) ? sh[t - off] : 0;
        __syncthreads();
        sh[t] += u;
        __syncthreads();
    }
    int total = sh[TILE - 1];

    if (t == 0) {
        long long st = (bid == 0)
            ? ((2LL << 32) | (unsigned)total)     // prefix (ex=0)
            : ((1LL << 32) | (unsigned)total);    // aggregate
        atomicExch((unsigned long long*)&g_state[bid], (unsigned long long)st);
        if (bid == 0) s_ex = 0;
    }

    if (bid > 0 && t < 32) {
        int ex = 0, base = bid - 1;
        while (true) {
            int j = base - t;
            long long st;
            if (j >= 0) st = *(volatile long long*)&g_state[j];
            else        st = (2LL << 32);          // virtual prefix 0
            int flag = (int)(st >> 32);
            int val  = (int)(st & 0xffffffffLL);
            unsigned rdy = __ballot_sync(0xffffffffu, flag != 0);
            if (rdy != 0xffffffffu) continue;      // someone not published yet
            unsigned pref = __ballot_sync(0xffffffffu, flag == 2);
            int firstP = (pref == 0) ? 32 : (__ffs(pref) - 1);
            int contrib = (t <= firstP) ? val : 0;
            #pragma unroll
            for (int o = 16; o >= 1; o >>= 1)
                contrib += __shfl_xor_sync(0xffffffffu, contrib, o);
            ex += contrib;
            if (firstP < 32) break;
            base -= 32;
        }
        if (t == 0) {
            s_ex = ex;
            atomicExch((unsigned long long*)&g_state[bid],
                       (unsigned long long)((2LL << 32) | (unsigned)(ex + total)));
        }
    }
    __syncthreads();
    if (i < N_NODES) g_off[i] = s_ex + sh[t] - c;   // exclusive prefix
}

// ---------------------------------------------------------------------------
// 3) fill source lists; atomically bumps g_off[c] (post: g_off[c]=off[c+1]).
//    Also re-zeroes g_state for the next replay.
// ---------------------------------------------------------------------------
__global__ void k_fill(const int* __restrict__ ei) {
    int t = blockIdx.x * blockDim.x + threadIdx.x;
    if (t < NB) g_state[t] = 0;
    if (t < N_EDGES / 4) {
        int4 r = ((const int4*)ei)[t];
        int4 c = ((const int4*)(ei + N_EDGES))[t];
        if ((unsigned)r.x < N_NODES && (unsigned)c.x < N_NODES)
            g_src[atomicAdd(&g_off[c.x], 1)] = r.x;
        if ((unsigned)r.y < N_NODES && (unsigned)c.y < N_NODES)
            g_src[atomicAdd(&g_off[c.y], 1)] = r.y;
        if ((unsigned)r.z < N_NODES && (unsigned)c.z < N_NODES)
            g_src[atomicAdd(&g_off[c.z], 1)] = r.z;
        if ((unsigned)r.w < N_NODES && (unsigned)c.w < N_NODES)
            g_src[atomicAdd(&g_off[c.w], 1)] = r.w;
    }
}

// ---------------------------------------------------------------------------
// 4) h1 = x @ W1 via tf32 mma.sync (m16n8k8). Block: 256 thr, 128 rows.
//    smem padded (36 / 136 words) -> conflict-free fragment loads.
// ---------------------------------------------------------------------------
__device__ __forceinline__ unsigned f2tf32(float f) {
    unsigned u;
    asm("cvt.rna.tf32.f32 %0, %1;" : "=r"(u) : "f"(f));
    return u;
}

__global__ __launch_bounds__(256) void k_gemm1(const float* __restrict__ x,
                                               const float* __restrict__ W) {
    __shared__ float xs[128 * 36];   // 128 rows x 32 cols, stride 36
    __shared__ float ws[32 * 136];   // 32 rows x 128 cols, stride 136

    const int tid  = threadIdx.x;
    const int warp = tid >> 5;
    const int lane = tid & 31;
    const int g    = lane >> 2;      // 0..7
    const int tig  = lane & 3;       // 0..3
    const int row0 = blockIdx.x * 128;

    float c[16][4];
    #pragma unroll
    for (int nt = 0; nt < 16; nt++)
        #pragma unroll
        for (int q = 0; q < 4; q++) c[nt][q] = 0.f;

    const float4* x4 = (const float4*)x;
    const float4* W4 = (const float4*)W;

    for (int kc = 0; kc < 4; kc++) {
        // stage x chunk [128 x 32]
        #pragma unroll
        for (int it = 0; it < 4; it++) {
            int idx = it * 256 + tid;          // 0..1023 float4s
            int r   = idx >> 3;
            int c4  = idx & 7;
            float4 v = make_float4(0.f, 0.f, 0.f, 0.f);
            if (row0 + r < N_NODES)
                v = x4[(size_t)(row0 + r) * 32 + kc * 8 + c4];
            float* d = &xs[r * 36 + c4 * 4];
            d[0] = v.x; d[1] = v.y; d[2] = v.z; d[3] = v.w;
        }
        // stage W chunk [32 x 128]
        #pragma unroll
        for (int it = 0; it < 4; it++) {
            int idx = it * 256 + tid;
            int k   = idx >> 5;
            int n4  = idx & 31;
            float4 v = W4[(kc * 32 + k) * 32 + n4];
            float* d = &ws[k * 136 + n4 * 4];
            d[0] = v.x; d[1] = v.y; d[2] = v.z; d[3] = v.w;
        }
        __syncthreads();

        #pragma unroll
        for (int ks = 0; ks < 4; ks++) {
            int ab = (warp * 16 + g) * 36 + ks * 8 + tig;
            unsigned a0 = f2tf32(xs[ab]);
            unsigned a1 = f2tf32(xs[ab + 8 * 36]);
            unsigned a2 = f2tf32(xs[ab + 4]);
            unsigned a3 = f2tf32(xs[ab + 8 * 36 + 4]);

            int bb = (ks * 8 + tig) * 136 + g;
            #pragma unroll
            for (int nt = 0; nt < 16; nt++) {
                unsigned b0 = f2tf32(ws[bb + nt * 8]);
                unsigned b1 = f2tf32(ws[bb + 4 * 136 + nt * 8]);
                asm("mma.sync.aligned.m16n8k8.row.col.f32.tf32.tf32.f32 "
                    "{%0,%1,%2,%3}, {%4,%5,%6,%7}, {%8,%9}, {%0,%1,%2,%3};"
                    : "+f"(c[nt][0]), "+f"(c[nt][1]), "+f"(c[nt][2]), "+f"(c[nt][3])
                    : "r"(a0), "r"(a1), "r"(a2), "r"(a3), "r"(b0), "r"(b1));
            }
        }
        __syncthreads();
    }

    // store: C frag m16n8 -> rows (g, g+8), cols (2*tig, 2*tig+1)
    float* h1 = (float*)g_h1;
    int m0 = row0 + warp * 16 + g;
    #pragma unroll
    for (int nt = 0; nt < 16; nt++) {
        int col = nt * 8 + 2 * tig;
        if (m0 < N_NODES)
            *(float2*)&h1[(size_t)m0 * F1 + col] = make_float2(c[nt][0], c[nt][1]);
        if (m0 + 8 < N_NODES)
            *(float2*)&h1[(size_t)(m0 + 8) * F1 + col] = make_float2(c[nt][2], c[nt][3]);
    }
}

// ---------------------------------------------------------------------------
// 5) fused layer-1: gather-aggregate + self-loop + bias + ReLU + @W2
// ---------------------------------------------------------------------------
__global__ __launch_bounds__(256) void k_layer1(const float* __restrict__ b1,
                                                const float* __restrict__ W2) {
    int row  = (blockIdx.x * 256 + threadIdx.x) >> 5;
    int lane = threadIdx.x & 31;
    if (row >= N_NODES) return;

    float dc = g_dinv[row];
    float d2 = dc * dc;

    float4 h   = g_h1[row * 32 + lane];
    float4 acc = make_float4(h.x * d2, h.y * d2, h.z * d2, h.w * d2);

    int e0 = (row > 0) ? g_off[row - 1] : 0;
    int e1 = g_off[row];
    for (int e = e0; e < e1; e++) {
        int   r = g_src[e];
        float w = g_dinv[r] * dc;
        float4 v = g_h1[r * 32 + lane];
        acc.x = fmaf(v.x, w, acc.x);
        acc.y = fmaf(v.y, w, acc.y);
        acc.z = fmaf(v.z, w, acc.z);
        acc.w = fmaf(v.w, w, acc.w);
    }

    float4 b = ((const float4*)b1)[lane];
    float v[4];
    v[0] = fmaxf(acc.x + b.x, 0.f);
    v[1] = fmaxf(acc.y + b.y, 0.f);
    v[2] = fmaxf(acc.z + b.z, 0.f);
    v[3] = fmaxf(acc.w + b.w, 0.f);

    float p[16];
    #pragma unroll
    for (int j = 0; j < 16; j++) p[j] = 0.f;

    #pragma unroll
    for (int q = 0; q < 4; q++) {
        int k = lane * 4 + q;
        #pragma unroll
        for (int j4 = 0; j4 < 4; j4++) {
            float4 ww = ((const float4*)W2)[k * 4 + j4];
            p[j4 * 4 + 0] = fmaf(v[q], ww.x, p[j4 * 4 + 0]);
            p[j4 * 4 + 1] = fmaf(v[q], ww.y, p[j4 * 4 + 1]);
            p[j4 * 4 + 2] = fmaf(v[q], ww.z, p[j4 * 4 + 2]);
            p[j4 * 4 + 3] = fmaf(v[q], ww.w, p[j4 * 4 + 3]);
        }
    }

    #pragma unroll
    for (int off = 16; off >= 1; off >>= 1)
        #pragma unroll
        for (int j = 0; j < 16; j++)
            p[j] += __shfl_xor_sync(0xffffffffu, p[j], off);

    if (lane < 16) ((float*)g_h2)[row * F2 + lane] = p[lane];
}

// ---------------------------------------------------------------------------
// 6) fused layer-2: gather-aggregate + self-loop + bias + log_softmax
// ---------------------------------------------------------------------------
__global__ __launch_bounds__(256) void k_layer2(const float* __restrict__ b2,
                                                float* __restrict__ out) {
    int row  = (blockIdx.x * 256 + threadIdx.x) >> 5;
    int lane = threadIdx.x & 31;
    if (row >= N_NODES) return;

    int j = lane & 15;
    float dc = g_dinv[row];
    float d2 = dc * dc;

    const float* h2 = (const float*)g_h2;
    float acc = h2[row * F2 + j] * d2;

    int e0 = (row > 0) ? g_off[row - 1] : 0;
    int e1 = g_off[row];
    for (int e = e0; e < e1; e++) {
        int   r = g_src[e];
        float w = g_dinv[r] * dc;
        acc = fmaf(h2[r * F2 + j], w, acc);
    }
    acc += b2[j];

    float m = acc;
    #pragma unroll
    for (int off = 8; off >= 1; off >>= 1)
        m = fmaxf(m, __shfl_xor_sync(0xffffffffu, m, off));

    float s = __expf(acc - m);
    #pragma unroll
    for (int off = 8; off >= 1; off >>= 1)
        s += __shfl_xor_sync(0xffffffffu, s, off);

    if (lane < 16) out[row * F2 + lane] = (acc - m) - logf(s);
}

// ---------------------------------------------------------------------------
extern "C" void kernel_launch(void* const* d_in, const int* in_sizes, int n_in,
                              void* d_out, int out_size) {
    const float* x  = (const float*)d_in[0];
    const int*   ei = (const int*)d_in[1];     // int32 (JAX x64 disabled)
    const float* W1 = (const float*)d_in[2];
    const float* b1 = (const float*)d_in[3];
    const float* W2 = (const float*)d_in[4];
    const float* b2 = (const float*)d_in[5];
    float* out = (float*)d_out;

    (void)in_sizes; (void)n_in; (void)out_size;

    k_count <<<(N_EDGES / 4 + 255) / 256, 256>>>(ei);
    k_scan  <<<NB, TILE>>>();
    k_fill  <<<(N_EDGES / 4 + 255) / 256, 256>>>(ei);
    k_gemm1 <<<(N_NODES + 127) / 128, 256>>>(x, W1);
    k_layer1<<<(N_NODES * 32 + 255) / 256, 256>>>(b1, W2);
    k_layer2<<<(N_NODES * 32 + 255) / 256, 256>>>(b2, out);
}